// round 4
// baseline (speedup 1.0000x reference)
#include <cuda_runtime.h>
#include <cstdint>

#define B_    64
#define T_    512
#define H_    1024
#define D_    512
#define GB_   4     // batch groups
#define CPG_  32    // CTAs (chunks) per group
#define BPG_  16    // batches per group
#define CHPC_ 32    // channels per CTA
#define NCTA_ (GB_*CPG_)
#define NTHR_ 512
#define SLOTS_ 4

// scratch (static __device__ arrays: zero at module load, allocation-free)
__device__ float  g_u[(size_t)T_ * B_ * H_];           // u drive [t][b][h]
__device__ float  g_stt[SLOTS_][B_][H_];               // state slots (depth 4)
__device__ float2 g_redp[SLOTS_][B_][CPG_];            // LN partials (depth 4)
__device__ int    g_flag[T_ + 1][GB_][CPG_];           // monotonic chunk-ready counters

// packed 2-wide fp32 FMA (sm_103a FFMA2, PTX-only)
__device__ __forceinline__ void fma2(unsigned long long& acc,
                                     unsigned long long a,
                                     unsigned long long b) {
    asm("fma.rn.f32x2 %0, %1, %2, %0;" : "+l"(acc) : "l"(a), "l"(b));
}
__device__ __forceinline__ float f2_lo(unsigned long long v) {
    return __uint_as_float((unsigned)(v & 0xffffffffull));
}
__device__ __forceinline__ float f2_hi(unsigned long long v) {
    return __uint_as_float((unsigned)(v >> 32));
}
__device__ __forceinline__ unsigned long long fdup(float x) {
    unsigned long long r;
    asm("mov.b64 %0, {%1, %1};" : "=l"(r) : "f"(x));
    return r;
}

// ---------------------------------------------------------------------------
// u[t][b][h] = sum_d x[b][t][d] * W_in[h][d] + b_in[h]  (f32x2 inner product)
// ---------------------------------------------------------------------------
__global__ __launch_bounds__(256) void u_gemm(const float* __restrict__ X,
                                              const float* __restrict__ Win,
                                              const float* __restrict__ bin) {
    __shared__ float As[8][128];
    __shared__ float Bs[8][128];
    int n0 = blockIdx.x * 128;
    int m0 = blockIdx.y * 128;
    int tid = threadIdx.x;
    int tm = tid >> 4, tn = tid & 15;

    unsigned long long acc2[8][4];
#pragma unroll
    for (int i = 0; i < 8; i++)
#pragma unroll
        for (int j = 0; j < 4; j++) acc2[i][j] = 0ull;

    int arow = tid >> 1;
    int ac4  = (tid & 1) * 4;
    const float* Aptr = X   + (size_t)(m0 + arow) * D_ + ac4;
    const float* Bptr = Win + (size_t)(n0 + arow) * D_ + ac4;

    for (int k0 = 0; k0 < D_; k0 += 8) {
        float4 av = *(const float4*)(Aptr + k0);
        float4 bv = *(const float4*)(Bptr + k0);
        As[ac4 + 0][arow] = av.x; As[ac4 + 1][arow] = av.y;
        As[ac4 + 2][arow] = av.z; As[ac4 + 3][arow] = av.w;
        Bs[ac4 + 0][arow] = bv.x; Bs[ac4 + 1][arow] = bv.y;
        Bs[ac4 + 2][arow] = bv.z; Bs[ac4 + 3][arow] = bv.w;
        __syncthreads();
#pragma unroll
        for (int kk = 0; kk < 8; kk++) {
            float rm[8];
            *(float4*)(rm)     = *(const float4*)&As[kk][tm * 8];
            *(float4*)(rm + 4) = *(const float4*)&As[kk][tm * 8 + 4];
            ulonglong2 t0 = *(const ulonglong2*)&Bs[kk][tn * 8];
            ulonglong2 t1 = *(const ulonglong2*)&Bs[kk][tn * 8 + 4];
            unsigned long long rnp[4] = {t0.x, t0.y, t1.x, t1.y};
#pragma unroll
            for (int i = 0; i < 8; i++) {
                unsigned long long rmd = fdup(rm[i]);
#pragma unroll
                for (int j = 0; j < 4; j++) fma2(acc2[i][j], rmd, rnp[j]);
            }
        }
        __syncthreads();
    }

    float bias[8];
    *(float4*)(bias)     = *(const float4*)&bin[n0 + tn * 8];
    *(float4*)(bias + 4) = *(const float4*)&bin[n0 + tn * 8 + 4];

#pragma unroll
    for (int i = 0; i < 8; i++) {
        int m  = m0 + tm * 8 + i;
        int tt = m & (T_ - 1);
        int bb = m >> 9;
        float* dst = g_u + ((size_t)tt * B_ + bb) * H_ + n0 + tn * 8;
        float4 v0, v1;
        v0.x = f2_lo(acc2[i][0]) + bias[0]; v0.y = f2_hi(acc2[i][0]) + bias[1];
        v0.z = f2_lo(acc2[i][1]) + bias[2]; v0.w = f2_hi(acc2[i][1]) + bias[3];
        v1.x = f2_lo(acc2[i][2]) + bias[4]; v1.y = f2_hi(acc2[i][2]) + bias[5];
        v1.z = f2_lo(acc2[i][3]) + bias[6]; v1.w = f2_hi(acc2[i][3]) + bias[7];
        *(float4*)(dst)     = v0;
        *(float4*)(dst + 4) = v1;
    }
}

// ---------------------------------------------------------------------------
// Persistent recurrence kernel, 512 threads/CTA, per-chunk flag pipeline.
// CTA (g,jc): batches [16g,16g+16), channels [32jc,32jc+32).
// K in 4 groups of 256; per-thread spins on exact producer chunk flags.
// Warp w owns channels {2w, 2w+1}; lane l ends owning (b=l>>1, c=l&1).
// ---------------------------------------------------------------------------
__global__ __launch_bounds__(512, 1) void rec_kernel(
    const float* __restrict__ Wst, const float* __restrict__ bst,
    const float* __restrict__ decay, const float* __restrict__ gamma,
    const float* __restrict__ beta, float* __restrict__ out) {
    extern __shared__ float smem[];
    float*  Wsm    = smem;                     // [32][1024] = 32768 floats
    float*  Ssm    = smem + CHPC_ * H_;        // 2 bufs x [16][256] = 8192 floats
    float2* red_sm = (float2*)(Ssm + 2 * BPG_ * 256);  // [16 warps][16 batches]
    float*  bcast  = (float*)(red_sm + 256);   // [16][2] mean/rstd + epoch

    int g   = blockIdx.x / CPG_;
    int jc  = blockIdx.x % CPG_;
    int ch0 = jc * CHPC_;
    int b0  = g * BPG_;
    int tid = threadIdx.x;
    int w = tid >> 5, l = tid & 31;

    // load W_state slice (rows ch0..ch0+31)
    {
        const float4* src = (const float4*)(Wst + (size_t)ch0 * H_);
        float4* dst = (float4*)Wsm;
        for (int v = tid; v < CHPC_ * H_ / 4; v += NTHR_) dst[v] = __ldg(src + v);
    }

    int myb  = l >> 1;
    int gb   = b0 + myb;
    int mych = ch0 + 2 * w + (l & 1);

    float dd = 1.0f / (1.0f + expf(-decay[mych]));
    float bs = bst[mych];
    float ga = gamma[mych], be = beta[mych];
    const unsigned FULL = 0xffffffffu;

    // producer-chunk flag indices for my two float4 loads per group
    int pc0 = l >> 3;        // + 8*sg
    int pc1 = 4 + (l >> 3);  // + 8*sg

    __syncthreads();

    float snp;   // my state value, in a register across steps
    int target;  // flag epoch target for this replay

    // ---------------- t = 0 : state is zero ----------------
    {
        float uv = __ldg(g_u + (size_t)gb * H_ + mych);
        snp = (1.0f - dd) * tanhf(uv + bs);
        float onb = __shfl_xor_sync(FULL, snp, 1);
        if ((l & 1) == 0)
            __stcg((float2*)&g_stt[1][gb][ch0 + 2 * w], make_float2(snp, onb));

        float ps = snp + onb, pq = snp * snp + onb * onb;
        if ((l & 1) == 0) red_sm[w * 16 + myb] = make_float2(ps, pq);
        __syncthreads();
        if (tid < BPG_) {
            float S = 0.0f, Q = 0.0f;
#pragma unroll
            for (int ww = 0; ww < 16; ww++) {
                float2 v = red_sm[ww * 16 + tid];
                S += v.x; Q += v.y;
            }
            __stcg(&g_redp[0][b0 + tid][jc], make_float2(S, Q));
        }
        __threadfence();
        __syncthreads();
        if (tid == 0) {
            int old = atomicAdd(&g_flag[1][g][jc], 1);
            bcast[32] = __int_as_float(old + 1);
        }
        __syncthreads();
        target = __float_as_int(bcast[32]);
    }

    // ---------------- main loop t = 1..T-1 ----------------
    for (int t = 1; t < T_; ++t) {
        int slot  = t & 3;
        int wslot = (t + 1) & 3;
        int rslot = (t - 1) & 3;
        float uv = __ldg(g_u + ((size_t)t * B_ + gb) * H_ + mych);

        unsigned long long acc[32];
#pragma unroll
        for (int o = 0; o < 32; o++) acc[o] = 0ull;

        const float4* srow = (const float4*)&g_stt[slot][b0][0];  // 256 f4/row

        // prologue: group seq(0); each thread waits on its own producers, loads, stores
        {
            int s0 = jc & 3;
            volatile int* f0 = &g_flag[t][g][8 * s0 + pc0];
            volatile int* f1 = &g_flag[t][g][8 * s0 + pc1];
            while (*f0 < target) {}
            while (*f1 < target) {}
            float4 r0 = __ldcg(&srow[w * 256 + s0 * 64 + l]);
            float4 r1 = __ldcg(&srow[w * 256 + s0 * 64 + l + 32]);
            float4* d = (float4*)Ssm;
            d[w * 64 + l]      = r0;
            d[w * 64 + l + 32] = r1;
            __syncthreads();
        }

#pragma unroll
        for (int i = 0; i < 4; ++i) {
            int sg  = (i + jc) & 3;
            int buf = i & 1;
            float4 n0, n1;
            if (i < 3) {
                int sgn = (i + 1 + jc) & 3;
                volatile int* f0 = &g_flag[t][g][8 * sgn + pc0];
                volatile int* f1 = &g_flag[t][g][8 * sgn + pc1];
                while (*f0 < target) {}
                while (*f1 < target) {}
                n0 = __ldcg(&srow[w * 256 + sgn * 64 + l]);
                n1 = __ldcg(&srow[w * 256 + sgn * 64 + l + 32]);
            }
            // GEMM on group sg from buffer buf
            {
                const float* sb = Ssm + buf * (BPG_ * 256);
                const float* wrow0 = Wsm + (2 * w) * H_ + sg * 256 + l * 4;
                const float* wrow1 = wrow0 + H_;
                ulonglong2 wa0 = *(const ulonglong2*)(wrow0);
                ulonglong2 wa1 = *(const ulonglong2*)(wrow0 + 128);
                ulonglong2 wb0 = *(const ulonglong2*)(wrow1);
                ulonglong2 wb1 = *(const ulonglong2*)(wrow1 + 128);
#pragma unroll
                for (int b = 0; b < 16; b++) {
                    ulonglong2 s0v = *(const ulonglong2*)&sb[b * 256 + l * 4];
                    ulonglong2 s1v = *(const ulonglong2*)&sb[b * 256 + 128 + l * 4];
                    fma2(acc[b * 2 + 0], s0v.x, wa0.x);
                    fma2(acc[b * 2 + 0], s0v.y, wa0.y);
                    fma2(acc[b * 2 + 0], s1v.x, wa1.x);
                    fma2(acc[b * 2 + 0], s1v.y, wa1.y);
                    fma2(acc[b * 2 + 1], s0v.x, wb0.x);
                    fma2(acc[b * 2 + 1], s0v.y, wb0.y);
                    fma2(acc[b * 2 + 1], s1v.x, wb1.x);
                    fma2(acc[b * 2 + 1], s1v.y, wb1.y);
                }
            }
            if (i < 3) {
                float4* d = (float4*)(Ssm + (buf ^ 1) * (BPG_ * 256));
                d[w * 64 + l]      = n0;
                d[w * 64 + l + 32] = n1;
                __syncthreads();
            }
        }
        __syncthreads();  // inherit all threads' flag observations (for g_redp read)

        // deferred LayerNorm for step t-1
        if (tid < BPG_) {
            const float4* rp = (const float4*)&g_redp[rslot][b0 + tid][0];
            float S = 0.0f, Q = 0.0f;
#pragma unroll
            for (int q = 0; q < 16; q++) {
                float4 v = __ldcg(&rp[q]);
                S += v.x + v.z; Q += v.y + v.w;
            }
            float mean = S * (1.0f / H_);
            float var  = Q * (1.0f / H_) - mean * mean;
            bcast[tid * 2 + 0] = mean;
            bcast[tid * 2 + 1] = rsqrtf(var + 1e-5f);
        }
        __syncthreads();
        {
            float mean = bcast[myb * 2 + 0], rstd = bcast[myb * 2 + 1];
            float y = (snp - mean) * rstd * ga + be;
            float yn = __shfl_xor_sync(FULL, y, 1);
            if ((l & 1) == 0)
                *(float2*)(out + ((size_t)gb * T_ + (t - 1)) * H_ + ch0 + 2 * w) =
                    make_float2(y, yn);
        }

        // reduce-scatter: collapse packed halves, 5-level butterfly (31 shuffles)
        float accf[32];
#pragma unroll
        for (int o = 0; o < 32; o++) accf[o] = f2_lo(acc[o]) + f2_hi(acc[o]);
#pragma unroll
        for (int delta = 16; delta >= 1; delta >>= 1) {
            bool up = (l & delta) != 0;
#pragma unroll
            for (int q = 0; q < delta; q++) {
                float send = up ? accf[q] : accf[q + delta];
                float recv = __shfl_xor_sync(FULL, send, delta);
                accf[q] = (up ? accf[q + delta] : accf[q]) + recv;
            }
        }

        float dr = tanhf(uv + accf[0] + bs);
        float sn = dd * snp + (1.0f - dd) * dr;
        float onb = __shfl_xor_sync(FULL, sn, 1);
        if ((l & 1) == 0)
            __stcg((float2*)&g_stt[wslot][gb][ch0 + 2 * w], make_float2(sn, onb));

        float ps = sn + onb, pq = sn * sn + onb * onb;
        if ((l & 1) == 0) red_sm[w * 16 + myb] = make_float2(ps, pq);
        __syncthreads();
        if (tid < BPG_) {
            float S = 0.0f, Q = 0.0f;
#pragma unroll
            for (int ww = 0; ww < 16; ww++) {
                float2 v = red_sm[ww * 16 + tid];
                S += v.x; Q += v.y;
            }
            __stcg(&g_redp[slot][b0 + tid][jc], make_float2(S, Q));
        }
        __threadfence();
        __syncthreads();
        if (tid == 0) atomicAdd(&g_flag[t + 1][g][jc], 1);

        snp = sn;
    }

    // ---------------- final LayerNorm for t = T-1 ----------------
    if (tid < 32) {
        volatile int* fp = &g_flag[T_][g][tid];
        while (*fp < target) {}
    }
    __syncthreads();
    {
        int rslot = (T_ - 1) & 3;
        if (tid < BPG_) {
            const float4* rp = (const float4*)&g_redp[rslot][b0 + tid][0];
            float S = 0.0f, Q = 0.0f;
#pragma unroll
            for (int q = 0; q < 16; q++) {
                float4 v = __ldcg(&rp[q]);
                S += v.x + v.z; Q += v.y + v.w;
            }
            float mean = S * (1.0f / H_);
            float var  = Q * (1.0f / H_) - mean * mean;
            bcast[tid * 2 + 0] = mean;
            bcast[tid * 2 + 1] = rsqrtf(var + 1e-5f);
        }
        __syncthreads();
        float mean = bcast[myb * 2 + 0], rstd = bcast[myb * 2 + 1];
        float y = (snp - mean) * rstd * ga + be;
        float yn = __shfl_xor_sync(FULL, y, 1);
        if ((l & 1) == 0)
            *(float2*)(out + ((size_t)gb * T_ + (T_ - 1)) * H_ + ch0 + 2 * w) =
                make_float2(y, yn);
    }
}

extern "C" void kernel_launch(void* const* d_in, const int* in_sizes, int n_in,
                              void* d_out, int out_size) {
    const float* x     = (const float*)d_in[0];
    const float* Win   = (const float*)d_in[1];
    const float* bin   = (const float*)d_in[2];
    const float* Wst   = (const float*)d_in[3];
    const float* bst   = (const float*)d_in[4];
    const float* decay = (const float*)d_in[5];
    const float* gamma = (const float*)d_in[6];
    const float* beta  = (const float*)d_in[7];
    float* out = (float*)d_out;

    const int smem_bytes = (CHPC_ * H_ + 2 * BPG_ * 256 + 512 + 40) * sizeof(float);
    cudaFuncSetAttribute(rec_kernel, cudaFuncAttributeMaxDynamicSharedMemorySize, smem_bytes);

    dim3 gg(H_ / 128, (B_ * T_) / 128);
    u_gemm<<<gg, 256>>>(x, Win, bin);
    rec_kernel<<<NCTA_, NTHR_, smem_bytes>>>(Wst, bst, decay, gamma, beta, out);
}

// round 5
// speedup vs baseline: 1.1540x; 1.1540x over previous
#include <cuda_runtime.h>
#include <cstdint>

#define B_    64
#define T_    512
#define H_    1024
#define D_    512
#define GB_   4     // batch groups
#define CPG_  32    // CTAs (chunks) per group
#define BPG_  16    // batches per group
#define CHPC_ 32    // channels per CTA
#define NCTA_ (GB_*CPG_)
#define NTHR_ 512
#define SLOTS_ 4

// scratch (static __device__ arrays: zero at module load, allocation-free)
__device__ float  g_u[(size_t)T_ * B_ * H_];           // u drive [t][b][h]
__device__ float  g_stt[SLOTS_][B_][H_];               // state slots (depth 4)
__device__ int    g_flag[T_ + 1][GB_][CPG_];           // monotonic chunk-ready counters

// packed 2-wide fp32 FMA (sm_103a FFMA2, PTX-only)
__device__ __forceinline__ void fma2(unsigned long long& acc,
                                     unsigned long long a,
                                     unsigned long long b) {
    asm("fma.rn.f32x2 %0, %1, %2, %0;" : "+l"(acc) : "l"(a), "l"(b));
}
__device__ __forceinline__ float f2_lo(unsigned long long v) {
    return __uint_as_float((unsigned)(v & 0xffffffffull));
}
__device__ __forceinline__ float f2_hi(unsigned long long v) {
    return __uint_as_float((unsigned)(v >> 32));
}
__device__ __forceinline__ unsigned long long fdup(float x) {
    unsigned long long r;
    asm("mov.b64 %0, {%1, %1};" : "=l"(r) : "f"(x));
    return r;
}

// ---------------------------------------------------------------------------
// u[t][b][h] = sum_d x[b][t][d] * W_in[h][d] + b_in[h]  (f32x2 inner product)
// ---------------------------------------------------------------------------
__global__ __launch_bounds__(256) void u_gemm(const float* __restrict__ X,
                                              const float* __restrict__ Win,
                                              const float* __restrict__ bin) {
    __shared__ float As[8][128];
    __shared__ float Bs[8][128];
    int n0 = blockIdx.x * 128;
    int m0 = blockIdx.y * 128;
    int tid = threadIdx.x;
    int tm = tid >> 4, tn = tid & 15;

    unsigned long long acc2[8][4];
#pragma unroll
    for (int i = 0; i < 8; i++)
#pragma unroll
        for (int j = 0; j < 4; j++) acc2[i][j] = 0ull;

    int arow = tid >> 1;
    int ac4  = (tid & 1) * 4;
    const float* Aptr = X   + (size_t)(m0 + arow) * D_ + ac4;
    const float* Bptr = Win + (size_t)(n0 + arow) * D_ + ac4;

    for (int k0 = 0; k0 < D_; k0 += 8) {
        float4 av = *(const float4*)(Aptr + k0);
        float4 bv = *(const float4*)(Bptr + k0);
        As[ac4 + 0][arow] = av.x; As[ac4 + 1][arow] = av.y;
        As[ac4 + 2][arow] = av.z; As[ac4 + 3][arow] = av.w;
        Bs[ac4 + 0][arow] = bv.x; Bs[ac4 + 1][arow] = bv.y;
        Bs[ac4 + 2][arow] = bv.z; Bs[ac4 + 3][arow] = bv.w;
        __syncthreads();
#pragma unroll
        for (int kk = 0; kk < 8; kk++) {
            float rm[8];
            *(float4*)(rm)     = *(const float4*)&As[kk][tm * 8];
            *(float4*)(rm + 4) = *(const float4*)&As[kk][tm * 8 + 4];
            ulonglong2 t0 = *(const ulonglong2*)&Bs[kk][tn * 8];
            ulonglong2 t1 = *(const ulonglong2*)&Bs[kk][tn * 8 + 4];
            unsigned long long rnp[4] = {t0.x, t0.y, t1.x, t1.y};
#pragma unroll
            for (int i = 0; i < 8; i++) {
                unsigned long long rmd = fdup(rm[i]);
#pragma unroll
                for (int j = 0; j < 4; j++) fma2(acc2[i][j], rmd, rnp[j]);
            }
        }
        __syncthreads();
    }

    float bias[8];
    *(float4*)(bias)     = *(const float4*)&bin[n0 + tn * 8];
    *(float4*)(bias + 4) = *(const float4*)&bin[n0 + tn * 8 + 4];

#pragma unroll
    for (int i = 0; i < 8; i++) {
        int m  = m0 + tm * 8 + i;
        int tt = m & (T_ - 1);
        int bb = m >> 9;
        float* dst = g_u + ((size_t)tt * B_ + bb) * H_ + n0 + tn * 8;
        float4 v0, v1;
        v0.x = f2_lo(acc2[i][0]) + bias[0]; v0.y = f2_hi(acc2[i][0]) + bias[1];
        v0.z = f2_lo(acc2[i][1]) + bias[2]; v0.w = f2_hi(acc2[i][1]) + bias[3];
        v1.x = f2_lo(acc2[i][2]) + bias[4]; v1.y = f2_hi(acc2[i][2]) + bias[5];
        v1.z = f2_lo(acc2[i][3]) + bias[6]; v1.w = f2_hi(acc2[i][3]) + bias[7];
        *(float4*)(dst)     = v0;
        *(float4*)(dst + 4) = v1;
    }
}

// ---------------------------------------------------------------------------
// Persistent recurrence kernel, 512 threads/CTA.
// CTA (g,jc): batches [16g,16g+16), channels [32jc,32jc+32).
// Warp w: channel quad cg=w&7 (4 channels) x batch half bh=w>>3 (8 batches).
// K in 4 groups of 256, double-buffered staging; warp w stages batch w and
// accumulates its LayerNorm sum/sumsq for free. No global LN reduction.
// ---------------------------------------------------------------------------
__global__ __launch_bounds__(512, 1) void rec_kernel(
    const float* __restrict__ Wst, const float* __restrict__ bst,
    const float* __restrict__ decay, const float* __restrict__ gamma,
    const float* __restrict__ beta, float* __restrict__ out) {
    extern __shared__ float smem[];
    float*  Wsm   = smem;                    // [32][1024] = 32768 floats
    float*  Ssm   = smem + CHPC_ * H_;       // 2 bufs x [16][256] = 8192 floats
    float*  bcast = Ssm + 2 * BPG_ * 256;    // [16]x{mean,rstd} + epoch

    int g   = blockIdx.x / CPG_;
    int jc  = blockIdx.x % CPG_;
    int ch0 = jc * CHPC_;
    int b0  = g * BPG_;
    int tid = threadIdx.x;
    int w = tid >> 5, l = tid & 31;
    int cg = w & 7, bh = w >> 3;

    // load W_state slice (rows ch0..ch0+31)
    {
        const float4* src = (const float4*)(Wst + (size_t)ch0 * H_);
        float4* dst = (float4*)Wsm;
        for (int v = tid; v < CHPC_ * H_ / 4; v += NTHR_) dst[v] = __ldg(src + v);
    }

    // output ownership after reduce-scatter: lane l owns acc index l
    int myb  = bh * 8 + (l >> 2);
    int gb   = b0 + myb;
    int mych = ch0 + cg * 4 + (l & 3);

    float dd = 1.0f / (1.0f + expf(-decay[mych]));
    float bs = bst[mych];
    float ga = gamma[mych], be = beta[mych];
    const unsigned FULL = 0xffffffffu;

    // producer-chunk flag offsets for this thread's two staged float4 per group
    int pc0 = l >> 3;        // + 8*sg
    int pc1 = 4 + (l >> 3);  // + 8*sg

    const float* wb0 = Wsm + (cg * 4) * H_ + l * 4;  // channel row base

    __syncthreads();

    float snp;   // my state value (channel mych, batch gb), register-resident
    int target;  // flag epoch target for this replay

    // ---------------- t = 0 : state is zero ----------------
    {
        float uv = __ldg(g_u + (size_t)gb * H_ + mych);
        snp = (1.0f - dd) * tanhf(uv + bs);
        __stcg(&g_stt[1][gb][mych], snp);
        __threadfence();
        __syncthreads();
        if (tid == 0) {
            int old = atomicAdd(&g_flag[1][g][jc], 1);
            bcast[33] = __int_as_float(old + 1);
        }
        __syncthreads();
        target = __float_as_int(bcast[33]);
    }

    // ---------------- main loop t = 1..T-1 ----------------
    for (int t = 1; t < T_; ++t) {
        int slot  = t & 3;
        int wslot = (t + 1) & 3;
        float uv = __ldg(g_u + ((size_t)t * B_ + gb) * H_ + mych);

        unsigned long long acc[32];
#pragma unroll
        for (int o = 0; o < 32; o++) acc[o] = 0ull;

        float ln_s = 0.0f, ln_q = 0.0f;  // batch-w LN partials (loader role)
        const float4* srow = (const float4*)&g_stt[slot][b0][0];  // 256 f4/row

        // prologue: stage group seq(0)
        {
            int s0 = jc & 3;
            volatile int* f0 = &g_flag[t][g][8 * s0 + pc0];
            volatile int* f1 = &g_flag[t][g][8 * s0 + pc1];
            while (*f0 < target) {}
            while (*f1 < target) {}
            float4 r0 = __ldcg(&srow[w * 256 + s0 * 64 + l]);
            float4 r1 = __ldcg(&srow[w * 256 + s0 * 64 + l + 32]);
            ln_s += r0.x + r0.y + r0.z + r0.w + r1.x + r1.y + r1.z + r1.w;
            ln_q += r0.x*r0.x + r0.y*r0.y + r0.z*r0.z + r0.w*r0.w
                  + r1.x*r1.x + r1.y*r1.y + r1.z*r1.z + r1.w*r1.w;
            float4* d = (float4*)Ssm;
            d[w * 64 + l]      = r0;
            d[w * 64 + l + 32] = r1;
            __syncthreads();
        }

#pragma unroll
        for (int i = 0; i < 4; ++i) {
            int sg  = (i + jc) & 3;
            int buf = i & 1;
            float4 n0, n1;
            if (i < 3) {
                int sgn = (i + 1 + jc) & 3;
                volatile int* f0 = &g_flag[t][g][8 * sgn + pc0];
                volatile int* f1 = &g_flag[t][g][8 * sgn + pc1];
                while (*f0 < target) {}
                while (*f1 < target) {}
                n0 = __ldcg(&srow[w * 256 + sgn * 64 + l]);
                n1 = __ldcg(&srow[w * 256 + sgn * 64 + l + 32]);
                ln_s += n0.x + n0.y + n0.z + n0.w + n1.x + n1.y + n1.z + n1.w;
                ln_q += n0.x*n0.x + n0.y*n0.y + n0.z*n0.z + n0.w*n0.w
                      + n1.x*n1.x + n1.y*n1.y + n1.z*n1.z + n1.w*n1.w;
            }
            // GEMM on group sg from buffer buf: two half-K passes (low W reg pressure)
            {
                const float* sb = Ssm + buf * (BPG_ * 256) + bh * (8 * 256);
                const float* wp = wb0 + sg * 256;
#pragma unroll
                for (int half = 0; half < 2; half++) {
                    ulonglong2 wv0 = *(const ulonglong2*)(wp + half * 128);
                    ulonglong2 wv1 = *(const ulonglong2*)(wp + half * 128 + H_);
                    ulonglong2 wv2 = *(const ulonglong2*)(wp + half * 128 + 2 * H_);
                    ulonglong2 wv3 = *(const ulonglong2*)(wp + half * 128 + 3 * H_);
#pragma unroll
                    for (int b = 0; b < 8; b++) {
                        ulonglong2 sv = *(const ulonglong2*)&sb[b * 256 + half * 128 + l * 4];
                        fma2(acc[b * 4 + 0], sv.x, wv0.x);
                        fma2(acc[b * 4 + 0], sv.y, wv0.y);
                        fma2(acc[b * 4 + 1], sv.x, wv1.x);
                        fma2(acc[b * 4 + 1], sv.y, wv1.y);
                        fma2(acc[b * 4 + 2], sv.x, wv2.x);
                        fma2(acc[b * 4 + 2], sv.y, wv2.y);
                        fma2(acc[b * 4 + 3], sv.x, wv3.x);
                        fma2(acc[b * 4 + 3], sv.y, wv3.y);
                    }
                }
            }
            if (i < 3) {
                float4* d = (float4*)(Ssm + (buf ^ 1) * (BPG_ * 256));
                d[w * 64 + l]      = n0;
                d[w * 64 + l + 32] = n1;
                __syncthreads();
            }
        }

        // reduce-scatter: collapse packed halves, 5-level butterfly (31 shuffles);
        // lane l ends owning acc index l = (b_loc<<2)|c_loc
        float accf[32];
#pragma unroll
        for (int o = 0; o < 32; o++) accf[o] = f2_lo(acc[o]) + f2_hi(acc[o]);
#pragma unroll
        for (int delta = 16; delta >= 1; delta >>= 1) {
            bool up = (l & delta) != 0;
#pragma unroll
            for (int q = 0; q < delta; q++) {
                float send = up ? accf[q] : accf[q + delta];
                float recv = __shfl_xor_sync(FULL, send, delta);
                accf[q] = (up ? accf[q + delta] : accf[q]) + recv;
            }
        }

        float dr = tanhf(uv + accf[0] + bs);
        float sn = dd * snp + (1.0f - dd) * dr;
        __stcg(&g_stt[wslot][gb][mych], sn);
        __threadfence();

        // LN stats for step t-1 (batch w), overlapping the fence latency
        {
#pragma unroll
            for (int delta = 16; delta >= 1; delta >>= 1) {
                ln_s += __shfl_xor_sync(FULL, ln_s, delta);
                ln_q += __shfl_xor_sync(FULL, ln_q, delta);
            }
            if (l == 0) {
                float mean = ln_s * (1.0f / H_);
                float var  = ln_q * (1.0f / H_) - mean * mean;
                bcast[w * 2 + 0] = mean;
                bcast[w * 2 + 1] = rsqrtf(var + 1e-5f);
            }
        }
        __syncthreads();
        if (tid == 0) atomicAdd(&g_flag[t + 1][g][jc], 1);

        // y(t-1) from register-resident snp
        {
            float mean = bcast[myb * 2 + 0], rstd = bcast[myb * 2 + 1];
            float y = (snp - mean) * rstd * ga + be;
            out[((size_t)gb * T_ + (t - 1)) * H_ + mych] = y;
        }
        snp = sn;
    }

    // ---------------- final LayerNorm for t = T-1 (state in slot 0) ----------------
    {
        float ln_s = 0.0f, ln_q = 0.0f;
        const float4* srow = (const float4*)&g_stt[0][b0][0];
#pragma unroll
        for (int sg = 0; sg < 4; sg++) {
            volatile int* f0 = &g_flag[T_][g][8 * sg + pc0];
            volatile int* f1 = &g_flag[T_][g][8 * sg + pc1];
            while (*f0 < target) {}
            while (*f1 < target) {}
            float4 r0 = __ldcg(&srow[w * 256 + sg * 64 + l]);
            float4 r1 = __ldcg(&srow[w * 256 + sg * 64 + l + 32]);
            ln_s += r0.x + r0.y + r0.z + r0.w + r1.x + r1.y + r1.z + r1.w;
            ln_q += r0.x*r0.x + r0.y*r0.y + r0.z*r0.z + r0.w*r0.w
                  + r1.x*r1.x + r1.y*r1.y + r1.z*r1.z + r1.w*r1.w;
        }
#pragma unroll
        for (int delta = 16; delta >= 1; delta >>= 1) {
            ln_s += __shfl_xor_sync(FULL, ln_s, delta);
            ln_q += __shfl_xor_sync(FULL, ln_q, delta);
        }
        if (l == 0) {
            float mean = ln_s * (1.0f / H_);
            float var  = ln_q * (1.0f / H_) - mean * mean;
            bcast[w * 2 + 0] = mean;
            bcast[w * 2 + 1] = rsqrtf(var + 1e-5f);
        }
        __syncthreads();
        float mean = bcast[myb * 2 + 0], rstd = bcast[myb * 2 + 1];
        float y = (snp - mean) * rstd * ga + be;
        out[((size_t)gb * T_ + (T_ - 1)) * H_ + mych] = y;
    }
}

extern "C" void kernel_launch(void* const* d_in, const int* in_sizes, int n_in,
                              void* d_out, int out_size) {
    const float* x     = (const float*)d_in[0];
    const float* Win   = (const float*)d_in[1];
    const float* bin   = (const float*)d_in[2];
    const float* Wst   = (const float*)d_in[3];
    const float* bst   = (const float*)d_in[4];
    const float* decay = (const float*)d_in[5];
    const float* gamma = (const float*)d_in[6];
    const float* beta  = (const float*)d_in[7];
    float* out = (float*)d_out;

    const int smem_bytes = (CHPC_ * H_ + 2 * BPG_ * 256 + 40) * sizeof(float);
    cudaFuncSetAttribute(rec_kernel, cudaFuncAttributeMaxDynamicSharedMemorySize, smem_bytes);

    dim3 gg(H_ / 128, (B_ * T_) / 128);
    u_gemm<<<gg, 256>>>(x, Win, bin);
    rec_kernel<<<NCTA_, NTHR_, smem_bytes>>>(Wst, bst, decay, gamma, beta, out);
}